// round 9
// baseline (speedup 1.0000x reference)
#include <cuda_runtime.h>
#include <cuda_bf16.h>
#include <cstdint>
#include <cstddef>

#define T_LEN 512
#define BATCH 128
#define EDIM  256
#define HDIM  256
#define NTAG  32
#define GDIM  1024  // 4*H
#define VOCAB 30000

// ---------------- device scratch (static, allocation-free) ----------------
__device__ __nv_bfloat16 g_h16[(size_t)2 * T_LEN * BATCH * HDIM];  // bf16 hidden
__device__ float g_em [(size_t)T_LEN * BATCH * NTAG];              // emissions
__device__ float g_llh[BATCH];
__device__ __nv_bfloat16 g_embed16[(size_t)VOCAB * EDIM];
__device__ __nv_bfloat16 g_wih16[(size_t)2 * GDIM * EDIM];
__device__ __nv_bfloat16 g_whh16[(size_t)2 * GDIM * HDIM];
__device__ __nv_bfloat16 g_pw16[(size_t)NTAG * 512];

// ---------------- helpers ----------------
__device__ __forceinline__ float tanh_mufu(float x) {
    float y;
    asm("tanh.approx.f32 %0, %1;" : "=f"(y) : "f"(x));
    return y;
}
__device__ __forceinline__ float sig_mufu(float x) {
    return fmaf(tanh_mufu(0.5f * x), 0.5f, 0.5f);
}

__device__ __forceinline__ uint32_t smem_u32(const void* p) {
    return (uint32_t)__cvta_generic_to_shared(p);
}
__device__ __forceinline__ void ldsm_x4(uint32_t* r, uint32_t addr) {
    asm volatile("ldmatrix.sync.aligned.m8n8.x4.shared.b16 {%0,%1,%2,%3}, [%4];"
                 : "=r"(r[0]), "=r"(r[1]), "=r"(r[2]), "=r"(r[3]) : "r"(addr));
}
__device__ __forceinline__ void ldsm_x2(uint32_t* r, uint32_t addr) {
    asm volatile("ldmatrix.sync.aligned.m8n8.x2.shared.b16 {%0,%1}, [%2];"
                 : "=r"(r[0]), "=r"(r[1]) : "r"(addr));
}
__device__ __forceinline__ void mma16816(float* d, const uint32_t* a, const uint32_t* b) {
    asm volatile("mma.sync.aligned.m16n8k16.row.col.f32.bf16.bf16.f32 "
                 "{%0,%1,%2,%3}, {%4,%5,%6,%7}, {%8,%9}, {%0,%1,%2,%3};"
                 : "+f"(d[0]), "+f"(d[1]), "+f"(d[2]), "+f"(d[3])
                 : "r"(a[0]), "r"(a[1]), "r"(a[2]), "r"(a[3]), "r"(b[0]), "r"(b[1]));
}
__device__ __forceinline__ uint32_t pack_bf16x2(float lo, float hi) {
    __nv_bfloat162 v = __floats2bfloat162_rn(lo, hi);
    return *reinterpret_cast<uint32_t*>(&v);
}

#define CLUSTER_ARRIVE() asm volatile("barrier.cluster.arrive.aligned;" ::: "memory")
#define CLUSTER_WAIT()   asm volatile("barrier.cluster.wait.aligned;" ::: "memory")

// ============================================================================
// K0: fp32 -> bf16 conversion of embed, W_ih, W_hh, proj_w
// ============================================================================
__global__ __launch_bounds__(256) void k0_convert(
    const float* __restrict__ embed,
    const float* __restrict__ wif, const float* __restrict__ wib,
    const float* __restrict__ whf, const float* __restrict__ whb,
    const float* __restrict__ pw)
{
    const int i0 = blockIdx.x * blockDim.x + threadIdx.x;
    const int stride = gridDim.x * blockDim.x;
    for (size_t i = i0; i < (size_t)VOCAB * EDIM; i += stride)
        g_embed16[i] = __float2bfloat16_rn(embed[i]);
    for (size_t i = i0; i < (size_t)GDIM * EDIM; i += stride) {
        g_wih16[i]                       = __float2bfloat16_rn(wif[i]);
        g_wih16[i + (size_t)GDIM * EDIM] = __float2bfloat16_rn(wib[i]);
        g_whh16[i]                       = __float2bfloat16_rn(whf[i]);
        g_whh16[i + (size_t)GDIM * HDIM] = __float2bfloat16_rn(whb[i]);
    }
    for (size_t i = i0; i < (size_t)NTAG * 512; i += stride)
        g_pw16[i] = __float2bfloat16_rn(pw[i]);
}

// ============================================================================
// K2: persistent bidirectional LSTM — R6 skeleton (8-CTA cluster, 16 batches,
//     256 thr, parallel per-dir clusters) with the gate-input GEMM FUSED in.
//     Per step: h-GEMM (critical path) + x-GEMM for step s+1 (off-path),
//     embed gather for step s+2 overlapping the cluster barrier.
//     grid(8,16): x = rank, y = dir*8 + grp.
// ============================================================================
// shared GEMM inner loop (M=16, warp-N=16, K=256), R6 fragment mapping
__device__ __forceinline__ void k2_gemm(uint32_t aAddr, uint32_t bAddr, float* gout,
                                        int w, int gid, int tig)
{
    float accE[2][4], accO[2][4];
#pragma unroll
    for (int nt = 0; nt < 2; nt++)
#pragma unroll
        for (int r = 0; r < 4; r++) { accE[nt][r] = 0.f; accO[nt][r] = 0.f; }
#pragma unroll
    for (int ks = 0; ks < 16; ks += 2) {
        uint32_t a0[4], a1[4], b0v[4], b1v[4];
        ldsm_x4(a0,  aAddr + (uint32_t)(ks * 32));
        ldsm_x4(b0v, bAddr + (uint32_t)(ks * 32));
        ldsm_x4(a1,  aAddr + (uint32_t)((ks + 1) * 32));
        ldsm_x4(b1v, bAddr + (uint32_t)((ks + 1) * 32));
        mma16816(accE[0], a0, b0v);
        mma16816(accE[1], a0, b0v + 2);
        mma16816(accO[0], a1, b1v);
        mma16816(accO[1], a1, b1v + 2);
    }
#pragma unroll
    for (int nt = 0; nt < 2; nt++) {
        const int n = w * 16 + nt * 8 + 2 * tig;
        *(float2*)(gout + gid * 132 + n) =
            make_float2(accE[nt][0] + accO[nt][0], accE[nt][1] + accO[nt][1]);
        *(float2*)(gout + (gid + 8) * 132 + n) =
            make_float2(accE[nt][2] + accO[nt][2], accE[nt][3] + accO[nt][3]);
    }
}

#define K2_W_BYTES   (128u * 528u)                 // one weight slice (W_hh or W_ih)
#define K2_HS_OFF    (2u * K2_W_BYTES)             // 135168
#define K2_XS_OFF    (K2_HS_OFF + 8448u)           // 143616: xs[2][16][528]
#define K2_GX_OFF    (K2_XS_OFF + 2u * 8448u)      // 160512: gx [16][132] f32
#define K2_GXI_OFF   (K2_GX_OFF + 8448u)           // 168960: gxi[2][16][132] f32
#define K2_SMEM      (K2_GXI_OFF + 2u * 8448u)     // 185856

__global__ void __launch_bounds__(256, 1) __cluster_dims__(8, 1, 1)
k2_lstm(const int* __restrict__ tokens,
        const float* __restrict__ bf, const float* __restrict__ bb_)
{
    extern __shared__ __align__(16) unsigned char sm[];
    unsigned char* Whh = sm;
    unsigned char* Wih = sm + K2_W_BYTES;
    unsigned char* hs  = sm + K2_HS_OFF;
    unsigned char* xs  = sm + K2_XS_OFF;
    float*         gx  = (float*)(sm + K2_GX_OFF);
    float*         gxi = (float*)(sm + K2_GXI_OFF);

    const int tid  = threadIdx.x;
    const int rank = blockIdx.x;
    const int grp  = blockIdx.y & 7;
    const int dir  = blockIdx.y >> 3;
    const int b0   = grp * 16;
    const size_t dirH = (size_t)dir * T_LEN * BATCH;
    const __nv_bfloat16* WhhG = g_whh16 + (size_t)dir * GDIM * HDIM;
    const __nv_bfloat16* WihG = g_wih16 + (size_t)dir * GDIM * EDIM;
    const float* BV = dir ? bb_ : bf;

    // load both weight slices (row n = q*32+j -> global row q*256+rank*32+j)
    for (int it = 0; it < 16; it++) {
        const int idx  = tid + it * 256;
        const int row  = idx >> 5;
        const int chnk = idx & 31;
        const int grow = (row >> 5) * 256 + rank * 32 + (row & 31);
        *(uint4*)(Whh + row * 528 + chnk * 16) =
            *(const uint4*)(WhhG + (size_t)grow * HDIM + chnk * 8);
        *(uint4*)(Wih + row * 528 + chnk * 16) =
            *(const uint4*)(WihG + (size_t)grow * EDIM + chnk * 8);
    }
    // zero h tile
    for (int i = tid; i < 528; i += 256) *(uint4*)(hs + i * 16) = make_uint4(0, 0, 0, 0);

    const int w = tid >> 5, lane = tid & 31;
    const int gid = lane >> 2, tig = lane & 3;
    const uint32_t aHs = smem_u32(hs) + (uint32_t)((lane & 15) * 528 + (lane >> 4) * 16);
    const uint32_t aXs = smem_u32(xs) + (uint32_t)((lane & 15) * 528 + (lane >> 4) * 16);
    const uint32_t bOff = (uint32_t)((w * 16 + ((lane >> 4) & 1) * 8 + (lane & 7)) * 528
                                     + ((lane >> 3) & 1) * 16);
    const uint32_t bHH = smem_u32(Whh) + bOff;
    const uint32_t bIH = smem_u32(Wih) + bOff;

    // update mapping: thread -> batches ubb, ubb+8 at hidden ujj
    const int ubb = tid >> 5;
    const int ujj = tid & 31;
    const int goff = rank * 32 + ujj;
    float c0 = 0.f, c1 = 0.f;
    float bias[4];
#pragma unroll
    for (int q = 0; q < 4; q++) bias[q] = BV[q * 256 + goff];

    // gather mapping: row = batch within group, ch = 16-elt chunk of 256
    const int xrow = tid >> 4, xch = tid & 15;

    // ---- prologue: x_{t(0)} -> xs[0] -> x-GEMM -> gxi[0]; then x_{t(1)} -> xs[0]
    {
        const int t0 = dir ? (T_LEN - 1) : 0;
        const int tok = tokens[(size_t)t0 * BATCH + b0 + xrow];
        const uint4* src = (const uint4*)(g_embed16 + (size_t)tok * EDIM + xch * 16);
        uint4 v0 = src[0], v1 = src[1];
        *(uint4*)(xs + xrow * 528 + xch * 32)      = v0;
        *(uint4*)(xs + xrow * 528 + xch * 32 + 16) = v1;
    }
    __syncthreads();
    k2_gemm(aXs, bIH, gxi, w, gid, tig);
    __syncthreads();
    {
        const int t1 = dir ? (T_LEN - 2) : 1;
        const int tok = tokens[(size_t)t1 * BATCH + b0 + xrow];
        const uint4* src = (const uint4*)(g_embed16 + (size_t)tok * EDIM + xch * 16);
        uint4 v0 = src[0], v1 = src[1];
        *(uint4*)(xs + xrow * 528 + xch * 32)      = v0;
        *(uint4*)(xs + xrow * 528 + xch * 32 + 16) = v1;
    }
    __syncthreads();

    for (int s = 0; s < T_LEN; s++) {
        const int t = dir ? (T_LEN - 1 - s) : s;

        // early loads: x tile for step s+2 (token -> embed row), latency hidden by GEMMs
        uint4 xv0, xv1;
        {
            const int sf = (s + 2 < T_LEN) ? (s + 2) : (T_LEN - 1);
            const int tf = dir ? (T_LEN - 1 - sf) : sf;
            const int tok = tokens[(size_t)tf * BATCH + b0 + xrow];
            const uint4* src = (const uint4*)(g_embed16 + (size_t)tok * EDIM + xch * 16);
            xv0 = src[0];
            xv1 = src[1];
        }

        // 1. h-GEMM (critical path) -> gx
        k2_gemm(aHs, bHH, gx, w, gid, tig);
        // 2. x-GEMM for step s+1 (reads xs[s&1] = x_{t(s+1)}) -> gxi[(s+1)&1]
        k2_gemm(aXs + (uint32_t)(s & 1) * 8448u, bIH, gxi + ((s + 1) & 1) * (16 * 132),
                w, gid, tig);
        __syncthreads();

        // 3. elementwise update (gx + gxi[s&1] + bias)
        const float* gxc = gxi + (s & 1) * (16 * 132);
        float xg0[4], xg1[4];
#pragma unroll
        for (int q = 0; q < 4; q++) {
            xg0[q] = gx[ubb * 132 + q * 32 + ujj]       + gxc[ubb * 132 + q * 32 + ujj]       + bias[q];
            xg1[q] = gx[(ubb + 8) * 132 + q * 32 + ujj] + gxc[(ubb + 8) * 132 + q * 32 + ujj] + bias[q];
        }
        c0 = sig_mufu(xg0[1]) * c0 + sig_mufu(xg0[0]) * tanh_mufu(xg0[2]);
        const float h0 = sig_mufu(xg0[3]) * tanh_mufu(c0);
        c1 = sig_mufu(xg1[1]) * c1 + sig_mufu(xg1[0]) * tanh_mufu(xg1[2]);
        const float h1 = sig_mufu(xg1[3]) * tanh_mufu(c1);

        __nv_bfloat16* hb = g_h16 + (dirH + (size_t)t * BATCH + b0) * HDIM + goff;
        hb[(size_t)ubb * HDIM]       = __float2bfloat16_rn(h0);
        hb[(size_t)(ubb + 8) * HDIM] = __float2bfloat16_rn(h1);

        CLUSTER_ARRIVE();   // release h stores cluster-wide

        // 4. stage x_{t(s+2)} into xs[(s+1)&1] (overlaps barrier wait)
        *(uint4*)(xs + (uint32_t)((s + 1) & 1) * 8448u + xrow * 528 + xch * 32)      = xv0;
        *(uint4*)(xs + (uint32_t)((s + 1) & 1) * 8448u + xrow * 528 + xch * 32 + 16) = xv1;

        CLUSTER_WAIT();     // acquire peers' h stores

        // 5. reload full h(t) tile (16 x 256 bf16)
        {
            const int row = tid >> 4, chnk = tid & 15;
            const uint4* src = (const uint4*)(g_h16 +
                (dirH + (size_t)t * BATCH + b0 + row) * HDIM + chnk * 16);
            uint4 v0 = src[0], v1 = src[1];
            *(uint4*)(hs + row * 528 + chnk * 32)      = v0;
            *(uint4*)(hs + row * 528 + chnk * 32 + 16) = v1;
        }
        __syncthreads();
    }
}

// ============================================================================
// K3: HMMA emissions GEMM (proven). M=65536, N=32, K=512.
// ============================================================================
#define K3_PW_STRIDE 1040u
#define K3_AS_STRIDE 144u
#define K3_PW_BYTES (32u * K3_PW_STRIDE)
#define K3_AS_BYTES (128u * K3_AS_STRIDE)
#define K3_SMEM     (K3_PW_BYTES + K3_AS_BYTES + 128u)

__global__ __launch_bounds__(256) void k3h(const float* __restrict__ pb)
{
    extern __shared__ __align__(16) unsigned char sm[];
    unsigned char* pwS = sm;
    unsigned char* As  = sm + K3_PW_BYTES;
    float*         pbs = (float*)(sm + K3_PW_BYTES + K3_AS_BYTES);

    const int tid = threadIdx.x;
#pragma unroll
    for (int it = 0; it < 8; it++) {
        const int idx = tid + it * 256;
        const int row = idx >> 6, ch = idx & 63;
        *(uint4*)(pwS + row * K3_PW_STRIDE + ch * 16) =
            *(const uint4*)(g_pw16 + (size_t)row * 512 + ch * 8);
    }
    if (tid < 32) pbs[tid] = pb[tid];

    const int w = tid >> 5, lane = tid & 31;
    const int gid = lane >> 2, tig = lane & 3;
    const size_t m0 = (size_t)blockIdx.x * 128;

    float acc[4][4];
#pragma unroll
    for (int nt = 0; nt < 4; nt++)
#pragma unroll
        for (int r = 0; r < 4; r++) acc[nt][r] = 0.f;

    const uint32_t As_b = smem_u32(As), pw_b = smem_u32(pwS);
    const uint32_t aAddr = As_b + (uint32_t)((w * 16 + (lane & 15)) * K3_AS_STRIDE + (lane >> 4) * 16);
    const uint32_t bAddr = pw_b + (uint32_t)((lane & 7) * K3_PW_STRIDE + ((lane >> 3) & 1) * 16);

    __syncthreads();

    for (int kc = 0; kc < 8; kc++) {
        uint4 v[4];
#pragma unroll
        for (int it = 0; it < 4; it++) {
            const int idx = tid + it * 256;
            const int row = idx >> 3, ch = idx & 7;
            const __nv_bfloat16* src = (kc < 4)
                ? g_h16 + (m0 + row) * HDIM + kc * 64
                : g_h16 + ((size_t)T_LEN * BATCH + m0 + row) * HDIM + (kc - 4) * 64;
            v[it] = *(const uint4*)(src + ch * 8);
        }
        __syncthreads();
#pragma unroll
        for (int it = 0; it < 4; it++) {
            const int idx = tid + it * 256;
            const int row = idx >> 3, ch = idx & 7;
            *(uint4*)(As + row * K3_AS_STRIDE + ch * 16) = v[it];
        }
        __syncthreads();

#pragma unroll
        for (int ks = 0; ks < 4; ks++) {
            uint32_t a[4];
            ldsm_x4(a, aAddr + (uint32_t)(ks * 32));
#pragma unroll
            for (int nt = 0; nt < 4; nt++) {
                uint32_t b[2];
                ldsm_x2(b, bAddr + (uint32_t)(nt * 8 * K3_PW_STRIDE + (kc * 4 + ks) * 32));
                mma16816(acc[nt], a, b);
            }
        }
    }

#pragma unroll
    for (int nt = 0; nt < 4; nt++) {
        const int n = nt * 8 + 2 * tig;
        const float2 bias = *(const float2*)(pbs + n);
        const size_t m = m0 + w * 16 + gid;
        *(float2*)(g_em + m * NTAG + n) =
            make_float2(acc[nt][0] + bias.x, acc[nt][1] + bias.y);
        *(float2*)(g_em + (m + 8) * NTAG + n) =
            make_float2(acc[nt][2] + bias.x, acc[nt][3] + bias.y);
    }
}

// ============================================================================
// K4: CRF per-batch llh (proven).
// ============================================================================
__global__ __launch_bounds__(32) void k4_crf(
    const int*   __restrict__ tags,
    const float* __restrict__ st, const float* __restrict__ et,
    const float* __restrict__ tr)
{
    __shared__ float psh[32];
    const int lane = threadIdx.x;
    const int b = blockIdx.x;

    float E[32];
#pragma unroll
    for (int i = 0; i < 32; i++) E[i] = __expf(tr[i * 32 + lane]);

    float alpha = st[lane] + g_em[(size_t)b * NTAG + lane];
    for (int t = 1; t < T_LEN; t++) {
        const float m = __shfl_sync(0xffffffffu, alpha, 0);
        psh[lane] = __expf(alpha - m);
        __syncwarp();
        float s0 = 0.f, s1 = 0.f, s2 = 0.f, s3 = 0.f;
#pragma unroll
        for (int i = 0; i < 32; i += 4) {
            s0 += psh[i]     * E[i];
            s1 += psh[i + 1] * E[i + 1];
            s2 += psh[i + 2] * E[i + 2];
            s3 += psh[i + 3] * E[i + 3];
        }
        __syncwarp();
        alpha = m + __logf((s0 + s1) + (s2 + s3)) + g_em[((size_t)t * BATCH + b) * NTAG + lane];
    }
    float v = alpha + et[lane];
    float m = v;
#pragma unroll
    for (int o = 16; o; o >>= 1) m = fmaxf(m, __shfl_xor_sync(0xffffffffu, m, o));
    float s = __expf(v - m);
#pragma unroll
    for (int o = 16; o; o >>= 1) s += __shfl_xor_sync(0xffffffffu, s, o);
    const float norm = m + __logf(s);

    float sc = 0.f;
    for (int t = lane; t < T_LEN; t += 32) {
        const int tg = tags[(size_t)t * BATCH + b];
        const float e = g_em[((size_t)t * BATCH + b) * NTAG + tg];
        if (t == 0) sc += st[tg] + e;
        else {
            const int tp = tags[(size_t)(t - 1) * BATCH + b];
            sc += tr[tp * NTAG + tg] + e;
        }
    }
#pragma unroll
    for (int o = 16; o; o >>= 1) sc += __shfl_xor_sync(0xffffffffu, sc, o);
    if (lane == 0) {
        sc += et[tags[(size_t)(T_LEN - 1) * BATCH + b]];
        g_llh[b] = sc - norm;
    }
}

// K5: deterministic scalar reduce
__global__ void k5_reduce(float* __restrict__ out)
{
    if (threadIdx.x == 0 && blockIdx.x == 0) {
        float s = 0.f;
        for (int b = 0; b < BATCH; b++) s += g_llh[b];
        out[0] = -s;
    }
}

// ============================================================================
extern "C" void kernel_launch(void* const* d_in, const int* in_sizes, int n_in,
                              void* d_out, int out_size)
{
    (void)in_sizes; (void)n_in; (void)out_size;
    const int*   tokens = (const int*)  d_in[0];
    const int*   tags   = (const int*)  d_in[1];
    // d_in[2] = mask (all true; unused)
    const float* embed  = (const float*)d_in[3];
    const float* w_ih_f = (const float*)d_in[4];
    const float* w_hh_f = (const float*)d_in[5];
    const float* b_f    = (const float*)d_in[6];
    const float* w_ih_b = (const float*)d_in[7];
    const float* w_hh_b = (const float*)d_in[8];
    const float* b_b    = (const float*)d_in[9];
    const float* proj_w = (const float*)d_in[10];
    const float* proj_b = (const float*)d_in[11];
    const float* start_trans = (const float*)d_in[12];
    const float* end_trans   = (const float*)d_in[13];
    const float* trans       = (const float*)d_in[14];
    float* out = (float*)d_out;

    cudaFuncSetAttribute(k2_lstm, cudaFuncAttributeMaxDynamicSharedMemorySize, K2_SMEM);
    cudaFuncSetAttribute(k3h,     cudaFuncAttributeMaxDynamicSharedMemorySize, K3_SMEM);

    k0_convert<<<4096, 256>>>(embed, w_ih_f, w_ih_b, w_hh_f, w_hh_b, proj_w);
    k2_lstm<<<dim3(8, 16), 256, K2_SMEM>>>(tokens, b_f, b_b);
    k3h<<<512, 256, K3_SMEM>>>(proj_b);
    k4_crf<<<128, 32>>>(tags, start_trans, end_trans, trans);
    k5_reduce<<<1, 32>>>(out);
}

// round 10
// speedup vs baseline: 1.5691x; 1.5691x over previous
#include <cuda_runtime.h>
#include <cuda_bf16.h>
#include <cstdint>
#include <cstddef>

#define T_LEN 512
#define BATCH 128
#define EDIM  256
#define HDIM  256
#define NTAG  32
#define GDIM  1024  // 4*H
#define VOCAB 30000

// ---------------- device scratch (static, allocation-free) ----------------
__device__ __nv_bfloat16 g_gi [(size_t)2 * T_LEN * BATCH * GDIM];  // bf16 gate inputs
__device__ __nv_bfloat16 g_h16[(size_t)2 * T_LEN * BATCH * HDIM];  // bf16 hidden
__device__ float g_em [(size_t)T_LEN * BATCH * NTAG];              // emissions
__device__ float g_llh[BATCH];
__device__ __nv_bfloat16 g_embed16[(size_t)VOCAB * EDIM];
__device__ __nv_bfloat16 g_wih16[(size_t)2 * GDIM * EDIM];
__device__ __nv_bfloat16 g_whh16[(size_t)2 * GDIM * HDIM];
__device__ __nv_bfloat16 g_pw16[(size_t)NTAG * 512];

// ---------------- helpers ----------------
__device__ __forceinline__ float tanh_mufu(float x) {
    float y;
    asm("tanh.approx.f32 %0, %1;" : "=f"(y) : "f"(x));
    return y;
}
__device__ __forceinline__ float sig_mufu(float x) {
    return fmaf(tanh_mufu(0.5f * x), 0.5f, 0.5f);
}

__device__ __forceinline__ uint32_t smem_u32(const void* p) {
    return (uint32_t)__cvta_generic_to_shared(p);
}
__device__ __forceinline__ void ldsm_x4(uint32_t* r, uint32_t addr) {
    asm volatile("ldmatrix.sync.aligned.m8n8.x4.shared.b16 {%0,%1,%2,%3}, [%4];"
                 : "=r"(r[0]), "=r"(r[1]), "=r"(r[2]), "=r"(r[3]) : "r"(addr));
}
__device__ __forceinline__ void ldsm_x2(uint32_t* r, uint32_t addr) {
    asm volatile("ldmatrix.sync.aligned.m8n8.x2.shared.b16 {%0,%1}, [%2];"
                 : "=r"(r[0]), "=r"(r[1]) : "r"(addr));
}
__device__ __forceinline__ void mma16816(float* d, const uint32_t* a, const uint32_t* b) {
    asm volatile("mma.sync.aligned.m16n8k16.row.col.f32.bf16.bf16.f32 "
                 "{%0,%1,%2,%3}, {%4,%5,%6,%7}, {%8,%9}, {%0,%1,%2,%3};"
                 : "+f"(d[0]), "+f"(d[1]), "+f"(d[2]), "+f"(d[3])
                 : "r"(a[0]), "r"(a[1]), "r"(a[2]), "r"(a[3]), "r"(b[0]), "r"(b[1]));
}
__device__ __forceinline__ uint32_t pack_bf16x2(float lo, float hi) {
    __nv_bfloat162 v = __floats2bfloat162_rn(lo, hi);
    return *reinterpret_cast<uint32_t*>(&v);
}

#define CLUSTER_ARRIVE() asm volatile("barrier.cluster.arrive.aligned;" ::: "memory")
#define CLUSTER_WAIT()   asm volatile("barrier.cluster.wait.aligned;" ::: "memory")

// ============================================================================
// K0: fp32 -> bf16 conversion of embed, W_ih, W_hh, proj_w
// ============================================================================
__global__ __launch_bounds__(256) void k0_convert(
    const float* __restrict__ embed,
    const float* __restrict__ wif, const float* __restrict__ wib,
    const float* __restrict__ whf, const float* __restrict__ whb,
    const float* __restrict__ pw)
{
    const int i0 = blockIdx.x * blockDim.x + threadIdx.x;
    const int stride = gridDim.x * blockDim.x;
    for (size_t i = i0; i < (size_t)VOCAB * EDIM; i += stride)
        g_embed16[i] = __float2bfloat16_rn(embed[i]);
    for (size_t i = i0; i < (size_t)GDIM * EDIM; i += stride) {
        g_wih16[i]                       = __float2bfloat16_rn(wif[i]);
        g_wih16[i + (size_t)GDIM * EDIM] = __float2bfloat16_rn(wib[i]);
        g_whh16[i]                       = __float2bfloat16_rn(whf[i]);
        g_whh16[i + (size_t)GDIM * HDIM] = __float2bfloat16_rn(whb[i]);
    }
    for (size_t i = i0; i < (size_t)NTAG * 512; i += stride)
        g_pw16[i] = __float2bfloat16_rn(pw[i]);
}

// ============================================================================
// K1: HMMA gate-input GEMM (proven R6; output packed bf16x2)
// ============================================================================
__global__ __launch_bounds__(256) void k1h(
    const int*   __restrict__ tokens,
    const float* __restrict__ bf, const float* __restrict__ bb_)
{
    __shared__ __align__(16) unsigned char As[128 * 80];
    __shared__ __align__(16) unsigned char Bs[64 * 80];
    __shared__ int toks[128];

    const int tid  = threadIdx.x;
    const int m0   = blockIdx.y * 128;
    const int nblk = blockIdx.x;
    const int dir  = nblk >> 4;
    const int n0   = (nblk & 15) * 64;
    const __nv_bfloat16* W16 = g_wih16 + (size_t)dir * GDIM * EDIM;
    const float* BV = dir ? bb_ : bf;

    if (tid < 128) toks[tid] = tokens[m0 + tid];

    const int w    = tid >> 5, lane = tid & 31;
    const int mw   = (w >> 1) * 32;
    const int nw   = (w & 1) * 32;
    const int gid  = lane >> 2, tig = lane & 3;

    float acc[2][4][4];
#pragma unroll
    for (int mt = 0; mt < 2; mt++)
#pragma unroll
        for (int nt = 0; nt < 4; nt++)
#pragma unroll
            for (int r = 0; r < 4; r++) acc[mt][nt][r] = 0.f;

    const int arow = tid >> 1, apart = tid & 1;
    const int brow = tid >> 2, bchunk = tid & 3;

    const uint32_t As_b = smem_u32(As);
    const uint32_t Bs_b = smem_u32(Bs);
    const uint32_t aAddrBase = As_b + (uint32_t)((mw + (lane & 15)) * 80 + (lane >> 4) * 16);
    const uint32_t bAddrBase = Bs_b + (uint32_t)((nw + (lane & 7)) * 80 + ((lane >> 3) & 1) * 16);

    __syncthreads();

    for (int kb = 0; kb < EDIM; kb += 32) {
        const uint4* asrc = (const uint4*)(g_embed16 + (size_t)toks[arow] * EDIM + kb + apart * 16);
        uint4 av0 = asrc[0];
        uint4 av1 = asrc[1];
        uint4 bv = *(const uint4*)(W16 + (size_t)(n0 + brow) * EDIM + kb + bchunk * 8);
        __syncthreads();
        *(uint4*)(As + arow * 80 + apart * 32)      = av0;
        *(uint4*)(As + arow * 80 + apart * 32 + 16) = av1;
        *(uint4*)(Bs + brow * 80 + bchunk * 16)     = bv;
        __syncthreads();

#pragma unroll
        for (int ks = 0; ks < 2; ks++) {
            uint32_t a[2][4], b[4][2];
#pragma unroll
            for (int mt = 0; mt < 2; mt++)
                ldsm_x4(a[mt], aAddrBase + (uint32_t)(mt * 16 * 80 + ks * 32));
#pragma unroll
            for (int nt = 0; nt < 4; nt++)
                ldsm_x2(b[nt], bAddrBase + (uint32_t)(nt * 8 * 80 + ks * 32));
#pragma unroll
            for (int mt = 0; mt < 2; mt++)
#pragma unroll
                for (int nt = 0; nt < 4; nt++)
                    mma16816(acc[mt][nt], a[mt], b[nt]);
        }
    }

    __nv_bfloat16* out = g_gi + (size_t)dir * T_LEN * BATCH * GDIM;
#pragma unroll
    for (int nt = 0; nt < 4; nt++) {
        const int n = n0 + nw + nt * 8 + 2 * tig;
        const float2 bias = *(const float2*)(BV + n);
#pragma unroll
        for (int mt = 0; mt < 2; mt++) {
            const int m = m0 + mw + mt * 16 + gid;
            *(uint32_t*)(out + (size_t)m * GDIM + n) =
                pack_bf16x2(acc[mt][nt][0] + bias.x, acc[mt][nt][1] + bias.y);
            *(uint32_t*)(out + (size_t)(m + 8) * GDIM + n) =
                pack_bf16x2(acc[mt][nt][2] + bias.x, acc[mt][nt][3] + bias.y);
        }
    }
}

// ============================================================================
// K2: persistent bidirectional LSTM (exact R6-proven 1692us version).
//     grid(8,16), cluster(8,1,1), 256 thr.
// ============================================================================
#define K2_WS_BYTES  (128u * 528u)
#define K2_HS_BYTES  (16u * 528u)
#define K2_GX_BYTES  (16u * 132u * 4u)
#define K2_SMEM      (K2_WS_BYTES + K2_HS_BYTES + K2_GX_BYTES)

__global__ void __launch_bounds__(256, 1) __cluster_dims__(8, 1, 1)
k2_lstm()
{
    extern __shared__ __align__(16) unsigned char sm_raw[];
    unsigned char* Wsm  = sm_raw;
    unsigned char* hs16 = sm_raw + K2_WS_BYTES;
    float*         gx   = (float*)(sm_raw + K2_WS_BYTES + K2_HS_BYTES);

    const int tid  = threadIdx.x;
    const int rank = blockIdx.x;
    const int grp  = blockIdx.y & 7;
    const int dir  = blockIdx.y >> 3;
    const int b0   = grp * 16;
    const __nv_bfloat16* Whh16 = g_whh16 + (size_t)dir * GDIM * HDIM;
    const size_t dirH = (size_t)dir * T_LEN * BATCH;

    for (int it = 0; it < 16; it++) {
        const int idx  = tid + it * 256;
        const int row  = idx >> 5;
        const int chnk = idx & 31;
        const int grow = (row >> 5) * 256 + rank * 32 + (row & 31);
        *(uint4*)(Wsm + row * 528 + chnk * 16) =
            *(const uint4*)(Whh16 + (size_t)grow * HDIM + chnk * 8);
    }
    for (int i = tid; i < 528; i += 256) *(uint4*)(hs16 + i * 16) = make_uint4(0,0,0,0);
    __syncthreads();

    const int w = tid >> 5, lane = tid & 31;
    const int gid = lane >> 2, tig = lane & 3;
    const uint32_t hs_b = smem_u32(hs16);
    const uint32_t Ws_b = smem_u32(Wsm);
    const uint32_t aAddrBase = hs_b + (uint32_t)((lane & 15) * 528 + (lane >> 4) * 16);
    const uint32_t bAddr4 = Ws_b + (uint32_t)((w * 16 + ((lane >> 4) & 1) * 8 + (lane & 7)) * 528
                                              + ((lane >> 3) & 1) * 16);

    const int ubb = tid >> 5;
    const int ujj = tid & 31;
    const int goff = rank * 32 + ujj;
    float c0 = 0.f, c1 = 0.f;

    float gir[2][4];
    {
        const int t0 = dir ? (T_LEN - 1) : 0;
        const __nv_bfloat16* gp = g_gi + (dirH + (size_t)t0 * BATCH + b0) * GDIM;
#pragma unroll
        for (int b2 = 0; b2 < 2; b2++)
#pragma unroll
            for (int q = 0; q < 4; q++)
                gir[b2][q] = __bfloat162float(gp[(size_t)(ubb + 8 * b2) * GDIM + q * 256 + goff]);
    }

    for (int s = 0; s < T_LEN; s++) {
        const int t = dir ? (T_LEN - 1 - s) : s;

        float accE[2][4], accO[2][4];
#pragma unroll
        for (int nt = 0; nt < 2; nt++)
#pragma unroll
            for (int r = 0; r < 4; r++) { accE[nt][r] = 0.f; accO[nt][r] = 0.f; }

#pragma unroll
        for (int ks = 0; ks < 16; ks += 2) {
            uint32_t a0[4], a1[4], b0v[4], b1v[4];
            ldsm_x4(a0,  aAddrBase + (uint32_t)(ks * 32));
            ldsm_x4(b0v, bAddr4    + (uint32_t)(ks * 32));
            ldsm_x4(a1,  aAddrBase + (uint32_t)((ks + 1) * 32));
            ldsm_x4(b1v, bAddr4    + (uint32_t)((ks + 1) * 32));
            mma16816(accE[0], a0, b0v);
            mma16816(accE[1], a0, b0v + 2);
            mma16816(accO[0], a1, b1v);
            mma16816(accO[1], a1, b1v + 2);
        }
#pragma unroll
        for (int nt = 0; nt < 2; nt++) {
            const int n = w * 16 + nt * 8 + 2 * tig;
            *(float2*)(gx + gid * 132 + n) =
                make_float2(accE[nt][0] + accO[nt][0], accE[nt][1] + accO[nt][1]);
            *(float2*)(gx + (gid + 8) * 132 + n) =
                make_float2(accE[nt][2] + accO[nt][2], accE[nt][3] + accO[nt][3]);
        }
        __syncthreads();

        float girN[2][4];
        {
            const int sn = (s + 1 < T_LEN) ? (s + 1) : s;
            const int tn = dir ? (T_LEN - 1 - sn) : sn;
            const __nv_bfloat16* gpn = g_gi + (dirH + (size_t)tn * BATCH + b0) * GDIM;
#pragma unroll
            for (int b2 = 0; b2 < 2; b2++)
#pragma unroll
                for (int q = 0; q < 4; q++)
                    girN[b2][q] = __bfloat162float(gpn[(size_t)(ubb + 8 * b2) * GDIM + q * 256 + goff]);
        }

        float xg0[4], xg1[4];
#pragma unroll
        for (int q = 0; q < 4; q++) {
            xg0[q] = gx[(size_t)ubb * 132 + q * 32 + ujj]       + gir[0][q];
            xg1[q] = gx[(size_t)(ubb + 8) * 132 + q * 32 + ujj] + gir[1][q];
        }
        c0 = sig_mufu(xg0[1]) * c0 + sig_mufu(xg0[0]) * tanh_mufu(xg0[2]);
        const float h0 = sig_mufu(xg0[3]) * tanh_mufu(c0);
        c1 = sig_mufu(xg1[1]) * c1 + sig_mufu(xg1[0]) * tanh_mufu(xg1[2]);
        const float h1 = sig_mufu(xg1[3]) * tanh_mufu(c1);

        __nv_bfloat16* hb = g_h16 + (dirH + (size_t)t * BATCH + b0) * HDIM + goff;
        hb[(size_t)ubb * HDIM]       = __float2bfloat16_rn(h0);
        hb[(size_t)(ubb + 8) * HDIM] = __float2bfloat16_rn(h1);

#pragma unroll
        for (int b2 = 0; b2 < 2; b2++)
#pragma unroll
            for (int q = 0; q < 4; q++)
                gir[b2][q] = girN[b2][q];

        CLUSTER_ARRIVE();
        CLUSTER_WAIT();

        {
            const int row = tid >> 4, chnk = tid & 15;
            const uint4* src = (const uint4*)(g_h16 + (dirH + (size_t)t * BATCH + b0 + row) * HDIM
                                              + chnk * 16);
            uint4 v0 = src[0], v1 = src[1];
            *(uint4*)(hs16 + row * 528 + chnk * 32)      = v0;
            *(uint4*)(hs16 + row * 528 + chnk * 32 + 16) = v1;
        }
        __syncthreads();
    }
}

// ============================================================================
// K3: HMMA emissions GEMM (proven). M=65536, N=32, K=512.
// ============================================================================
#define K3_PW_STRIDE 1040u
#define K3_AS_STRIDE 144u
#define K3_PW_BYTES (32u * K3_PW_STRIDE)
#define K3_AS_BYTES (128u * K3_AS_STRIDE)
#define K3_SMEM     (K3_PW_BYTES + K3_AS_BYTES + 128u)

__global__ __launch_bounds__(256) void k3h(const float* __restrict__ pb)
{
    extern __shared__ __align__(16) unsigned char sm[];
    unsigned char* pwS = sm;
    unsigned char* As  = sm + K3_PW_BYTES;
    float*         pbs = (float*)(sm + K3_PW_BYTES + K3_AS_BYTES);

    const int tid = threadIdx.x;
#pragma unroll
    for (int it = 0; it < 8; it++) {
        const int idx = tid + it * 256;
        const int row = idx >> 6, ch = idx & 63;
        *(uint4*)(pwS + row * K3_PW_STRIDE + ch * 16) =
            *(const uint4*)(g_pw16 + (size_t)row * 512 + ch * 8);
    }
    if (tid < 32) pbs[tid] = pb[tid];

    const int w = tid >> 5, lane = tid & 31;
    const int gid = lane >> 2, tig = lane & 3;
    const size_t m0 = (size_t)blockIdx.x * 128;

    float acc[4][4];
#pragma unroll
    for (int nt = 0; nt < 4; nt++)
#pragma unroll
        for (int r = 0; r < 4; r++) acc[nt][r] = 0.f;

    const uint32_t As_b = smem_u32(As), pw_b = smem_u32(pwS);
    const uint32_t aAddr = As_b + (uint32_t)((w * 16 + (lane & 15)) * K3_AS_STRIDE + (lane >> 4) * 16);
    const uint32_t bAddr = pw_b + (uint32_t)((lane & 7) * K3_PW_STRIDE + ((lane >> 3) & 1) * 16);

    __syncthreads();

    for (int kc = 0; kc < 8; kc++) {
        uint4 v[4];
#pragma unroll
        for (int it = 0; it < 4; it++) {
            const int idx = tid + it * 256;
            const int row = idx >> 3, ch = idx & 7;
            const __nv_bfloat16* src = (kc < 4)
                ? g_h16 + (m0 + row) * HDIM + kc * 64
                : g_h16 + ((size_t)T_LEN * BATCH + m0 + row) * HDIM + (kc - 4) * 64;
            v[it] = *(const uint4*)(src + ch * 8);
        }
        __syncthreads();
#pragma unroll
        for (int it = 0; it < 4; it++) {
            const int idx = tid + it * 256;
            const int row = idx >> 3, ch = idx & 7;
            *(uint4*)(As + row * K3_AS_STRIDE + ch * 16) = v[it];
        }
        __syncthreads();

#pragma unroll
        for (int ks = 0; ks < 4; ks++) {
            uint32_t a[4];
            ldsm_x4(a, aAddr + (uint32_t)(ks * 32));
#pragma unroll
            for (int nt = 0; nt < 4; nt++) {
                uint32_t b[2];
                ldsm_x2(b, bAddr + (uint32_t)(nt * 8 * K3_PW_STRIDE + (kc * 4 + ks) * 32));
                mma16816(acc[nt], a, b);
            }
        }
    }

#pragma unroll
    for (int nt = 0; nt < 4; nt++) {
        const int n = nt * 8 + 2 * tig;
        const float2 bias = *(const float2*)(pbs + n);
        const size_t m = m0 + w * 16 + gid;
        *(float2*)(g_em + m * NTAG + n) =
            make_float2(acc[nt][0] + bias.x, acc[nt][1] + bias.y);
        *(float2*)(g_em + (m + 8) * NTAG + n) =
            make_float2(acc[nt][2] + bias.x, acc[nt][3] + bias.y);
    }
}

// ============================================================================
// K4: CRF per-batch llh. 64 blocks x 1 warp; lane = tag; 2 batches per warp
//     (independent alpha chains give ILP), emissions prefetched 1 step ahead.
// ============================================================================
__global__ __launch_bounds__(32) void k4_crf(
    const int*   __restrict__ tags,
    const float* __restrict__ st, const float* __restrict__ et,
    const float* __restrict__ tr)
{
    __shared__ float psh[2][32];
    const int lane = threadIdx.x;
    const int b0 = blockIdx.x * 2;

    float E[32];
#pragma unroll
    for (int i = 0; i < 32; i++) E[i] = __expf(tr[i * 32 + lane]);

    float al0 = st[lane] + g_em[(size_t)b0 * NTAG + lane];
    float al1 = st[lane] + g_em[(size_t)(b0 + 1) * NTAG + lane];
    // prefetch emissions for t=1
    float em0 = g_em[((size_t)1 * BATCH + b0) * NTAG + lane];
    float em1 = g_em[((size_t)1 * BATCH + b0 + 1) * NTAG + lane];

    for (int t = 1; t < T_LEN; t++) {
        // prefetch t+1 emissions (off the serial chain)
        float em0n = 0.f, em1n = 0.f;
        if (t + 1 < T_LEN) {
            em0n = g_em[((size_t)(t + 1) * BATCH + b0) * NTAG + lane];
            em1n = g_em[((size_t)(t + 1) * BATCH + b0 + 1) * NTAG + lane];
        }
        const float m0 = __shfl_sync(0xffffffffu, al0, 0);
        const float m1 = __shfl_sync(0xffffffffu, al1, 0);
        psh[0][lane] = __expf(al0 - m0);
        psh[1][lane] = __expf(al1 - m1);
        __syncwarp();
        float s0a = 0.f, s0b = 0.f, s0c = 0.f, s0d = 0.f;
        float s1a = 0.f, s1b = 0.f, s1c = 0.f, s1d = 0.f;
#pragma unroll
        for (int i = 0; i < 32; i += 4) {
            s0a += psh[0][i]     * E[i];
            s0b += psh[0][i + 1] * E[i + 1];
            s0c += psh[0][i + 2] * E[i + 2];
            s0d += psh[0][i + 3] * E[i + 3];
            s1a += psh[1][i]     * E[i];
            s1b += psh[1][i + 1] * E[i + 1];
            s1c += psh[1][i + 2] * E[i + 2];
            s1d += psh[1][i + 3] * E[i + 3];
        }
        __syncwarp();
        al0 = m0 + __logf((s0a + s0b) + (s0c + s0d)) + em0;
        al1 = m1 + __logf((s1a + s1b) + (s1c + s1d)) + em1;
        em0 = em0n;
        em1 = em1n;
    }

#pragma unroll
    for (int bb = 0; bb < 2; bb++) {
        const int b = b0 + bb;
        const float alpha = bb ? al1 : al0;
        float v = alpha + et[lane];
        float m = v;
#pragma unroll
        for (int o = 16; o; o >>= 1) m = fmaxf(m, __shfl_xor_sync(0xffffffffu, m, o));
        float s = __expf(v - m);
#pragma unroll
        for (int o = 16; o; o >>= 1) s += __shfl_xor_sync(0xffffffffu, s, o);
        const float norm = m + __logf(s);

        float sc = 0.f;
        for (int t = lane; t < T_LEN; t += 32) {
            const int tg = tags[(size_t)t * BATCH + b];
            const float e = g_em[((size_t)t * BATCH + b) * NTAG + tg];
            if (t == 0) sc += st[tg] + e;
            else {
                const int tp = tags[(size_t)(t - 1) * BATCH + b];
                sc += tr[tp * NTAG + tg] + e;
            }
        }
#pragma unroll
        for (int o = 16; o; o >>= 1) sc += __shfl_xor_sync(0xffffffffu, sc, o);
        if (lane == 0) {
            sc += et[tags[(size_t)(T_LEN - 1) * BATCH + b]];
            g_llh[b] = sc - norm;
        }
    }
}

// K5: deterministic scalar reduce
__global__ void k5_reduce(float* __restrict__ out)
{
    if (threadIdx.x == 0 && blockIdx.x == 0) {
        float s = 0.f;
        for (int b = 0; b < BATCH; b++) s += g_llh[b];
        out[0] = -s;
    }
}

// ============================================================================
extern "C" void kernel_launch(void* const* d_in, const int* in_sizes, int n_in,
                              void* d_out, int out_size)
{
    (void)in_sizes; (void)n_in; (void)out_size;
    const int*   tokens = (const int*)  d_in[0];
    const int*   tags   = (const int*)  d_in[1];
    // d_in[2] = mask (all true; unused)
    const float* embed  = (const float*)d_in[3];
    const float* w_ih_f = (const float*)d_in[4];
    const float* w_hh_f = (const float*)d_in[5];
    const float* b_f    = (const float*)d_in[6];
    const float* w_ih_b = (const float*)d_in[7];
    const float* w_hh_b = (const float*)d_in[8];
    const float* b_b    = (const float*)d_in[9];
    const float* proj_w = (const float*)d_in[10];
    const float* proj_b = (const float*)d_in[11];
    const float* start_trans = (const float*)d_in[12];
    const float* end_trans   = (const float*)d_in[13];
    const float* trans       = (const float*)d_in[14];
    float* out = (float*)d_out;

    cudaFuncSetAttribute(k2_lstm, cudaFuncAttributeMaxDynamicSharedMemorySize, K2_SMEM);
    cudaFuncSetAttribute(k3h,     cudaFuncAttributeMaxDynamicSharedMemorySize, K3_SMEM);

    k0_convert<<<4096, 256>>>(embed, w_ih_f, w_ih_b, w_hh_f, w_hh_b, proj_w);
    k1h<<<dim3(32, 512), 256>>>(tokens, b_f, b_b);
    k2_lstm<<<dim3(8, 16), 256, K2_SMEM>>>();
    k3h<<<512, 256, K3_SMEM>>>(proj_b);
    k4_crf<<<64, 32>>>(tags, start_trans, end_trans, trans);
    k5_reduce<<<1, 32>>>(out);
}

// round 11
// speedup vs baseline: 1.6319x; 1.0400x over previous
#include <cuda_runtime.h>
#include <cuda_bf16.h>
#include <cstdint>
#include <cstddef>

#define T_LEN 512
#define BATCH 128
#define EDIM  256
#define HDIM  256
#define NTAG  32
#define GDIM  1024  // 4*H
#define VOCAB 30000
#define TMID  255   // fwd computes alpha_255; bwd computes beta_255

// ---------------- device scratch (static, allocation-free) ----------------
__device__ __nv_bfloat16 g_gi [(size_t)2 * T_LEN * BATCH * GDIM];  // bf16 gate inputs
__device__ __nv_bfloat16 g_h16[(size_t)2 * T_LEN * BATCH * HDIM];  // bf16 hidden
__device__ float g_em [(size_t)T_LEN * BATCH * NTAG];              // emissions
__device__ float g_llh[BATCH];
__device__ float g_amid[BATCH * NTAG];                             // alpha at t=TMID
__device__ float g_bmid[BATCH * NTAG];                             // beta  at t=TMID
__device__ __nv_bfloat16 g_embed16[(size_t)VOCAB * EDIM];
__device__ __nv_bfloat16 g_wih16[(size_t)2 * GDIM * EDIM];
__device__ __nv_bfloat16 g_whh16[(size_t)2 * GDIM * HDIM];
__device__ __nv_bfloat16 g_pw16[(size_t)NTAG * 512];

// ---------------- helpers ----------------
__device__ __forceinline__ float tanh_mufu(float x) {
    float y;
    asm("tanh.approx.f32 %0, %1;" : "=f"(y) : "f"(x));
    return y;
}
__device__ __forceinline__ float sig_mufu(float x) {
    return fmaf(tanh_mufu(0.5f * x), 0.5f, 0.5f);
}

__device__ __forceinline__ uint32_t smem_u32(const void* p) {
    return (uint32_t)__cvta_generic_to_shared(p);
}
__device__ __forceinline__ void ldsm_x4(uint32_t* r, uint32_t addr) {
    asm volatile("ldmatrix.sync.aligned.m8n8.x4.shared.b16 {%0,%1,%2,%3}, [%4];"
                 : "=r"(r[0]), "=r"(r[1]), "=r"(r[2]), "=r"(r[3]) : "r"(addr));
}
__device__ __forceinline__ void ldsm_x2(uint32_t* r, uint32_t addr) {
    asm volatile("ldmatrix.sync.aligned.m8n8.x2.shared.b16 {%0,%1}, [%2];"
                 : "=r"(r[0]), "=r"(r[1]) : "r"(addr));
}
__device__ __forceinline__ void mma16816(float* d, const uint32_t* a, const uint32_t* b) {
    asm volatile("mma.sync.aligned.m16n8k16.row.col.f32.bf16.bf16.f32 "
                 "{%0,%1,%2,%3}, {%4,%5,%6,%7}, {%8,%9}, {%0,%1,%2,%3};"
                 : "+f"(d[0]), "+f"(d[1]), "+f"(d[2]), "+f"(d[3])
                 : "r"(a[0]), "r"(a[1]), "r"(a[2]), "r"(a[3]), "r"(b[0]), "r"(b[1]));
}
__device__ __forceinline__ uint32_t pack_bf16x2(float lo, float hi) {
    __nv_bfloat162 v = __floats2bfloat162_rn(lo, hi);
    return *reinterpret_cast<uint32_t*>(&v);
}

#define CLUSTER_ARRIVE() asm volatile("barrier.cluster.arrive.aligned;" ::: "memory")
#define CLUSTER_WAIT()   asm volatile("barrier.cluster.wait.aligned;" ::: "memory")

// ============================================================================
// K0: fp32 -> bf16 conversion of embed, W_ih, W_hh, proj_w
// ============================================================================
__global__ __launch_bounds__(256) void k0_convert(
    const float* __restrict__ embed,
    const float* __restrict__ wif, const float* __restrict__ wib,
    const float* __restrict__ whf, const float* __restrict__ whb,
    const float* __restrict__ pw)
{
    const int i0 = blockIdx.x * blockDim.x + threadIdx.x;
    const int stride = gridDim.x * blockDim.x;
    for (size_t i = i0; i < (size_t)VOCAB * EDIM; i += stride)
        g_embed16[i] = __float2bfloat16_rn(embed[i]);
    for (size_t i = i0; i < (size_t)GDIM * EDIM; i += stride) {
        g_wih16[i]                       = __float2bfloat16_rn(wif[i]);
        g_wih16[i + (size_t)GDIM * EDIM] = __float2bfloat16_rn(wib[i]);
        g_whh16[i]                       = __float2bfloat16_rn(whf[i]);
        g_whh16[i + (size_t)GDIM * HDIM] = __float2bfloat16_rn(whb[i]);
    }
    for (size_t i = i0; i < (size_t)NTAG * 512; i += stride)
        g_pw16[i] = __float2bfloat16_rn(pw[i]);
}

// ============================================================================
// K1: HMMA gate-input GEMM, double-buffered smem (1 barrier/chunk, loads
//     for chunk k+1 register-staged before computing chunk k).
// ============================================================================
__global__ __launch_bounds__(256) void k1h(
    const int*   __restrict__ tokens,
    const float* __restrict__ bf, const float* __restrict__ bb_)
{
    __shared__ __align__(16) unsigned char As[2 * 128 * 80];
    __shared__ __align__(16) unsigned char Bs[2 * 64 * 80];
    __shared__ int toks[128];

    const int tid  = threadIdx.x;
    const int m0   = blockIdx.y * 128;
    const int nblk = blockIdx.x;
    const int dir  = nblk >> 4;
    const int n0   = (nblk & 15) * 64;
    const __nv_bfloat16* W16 = g_wih16 + (size_t)dir * GDIM * EDIM;
    const float* BV = dir ? bb_ : bf;

    if (tid < 128) toks[tid] = tokens[m0 + tid];

    const int w    = tid >> 5, lane = tid & 31;
    const int mw   = (w >> 1) * 32;
    const int nw   = (w & 1) * 32;
    const int gid  = lane >> 2, tig = lane & 3;

    float acc[2][4][4];
#pragma unroll
    for (int mt = 0; mt < 2; mt++)
#pragma unroll
        for (int nt = 0; nt < 4; nt++)
#pragma unroll
            for (int r = 0; r < 4; r++) acc[mt][nt][r] = 0.f;

    const int arow = tid >> 1, apart = tid & 1;
    const int brow = tid >> 2, bchunk = tid & 3;

    const uint32_t As_b = smem_u32(As);
    const uint32_t Bs_b = smem_u32(Bs);
    const uint32_t aAddrBase = As_b + (uint32_t)((mw + (lane & 15)) * 80 + (lane >> 4) * 16);
    const uint32_t bAddrBase = Bs_b + (uint32_t)((nw + (lane & 7)) * 80 + ((lane >> 3) & 1) * 16);

    __syncthreads();   // toks visible

    // preload chunk 0 into buffer 0
    uint4 av0, av1, bv;
    {
        const uint4* asrc = (const uint4*)(g_embed16 + (size_t)toks[arow] * EDIM + apart * 16);
        av0 = asrc[0];
        av1 = asrc[1];
        bv = *(const uint4*)(W16 + (size_t)(n0 + brow) * EDIM + bchunk * 8);
    }
    *(uint4*)(As + arow * 80 + apart * 32)      = av0;
    *(uint4*)(As + arow * 80 + apart * 32 + 16) = av1;
    *(uint4*)(Bs + brow * 80 + bchunk * 16)     = bv;
    __syncthreads();

    int p = 0;
#pragma unroll
    for (int kb8 = 0; kb8 < 8; kb8++) {
        // stage next chunk's globals into registers (latency hidden under mma)
        if (kb8 < 7) {
            const int kb = (kb8 + 1) * 32;
            const uint4* asrc = (const uint4*)(g_embed16 + (size_t)toks[arow] * EDIM + kb + apart * 16);
            av0 = asrc[0];
            av1 = asrc[1];
            bv = *(const uint4*)(W16 + (size_t)(n0 + brow) * EDIM + kb + bchunk * 8);
        }

        const uint32_t aB = aAddrBase + (uint32_t)p * 10240u;
        const uint32_t bB = bAddrBase + (uint32_t)p * 5120u;
#pragma unroll
        for (int ks = 0; ks < 2; ks++) {
            uint32_t a[2][4], b[4][2];
#pragma unroll
            for (int mt = 0; mt < 2; mt++)
                ldsm_x4(a[mt], aB + (uint32_t)(mt * 16 * 80 + ks * 32));
#pragma unroll
            for (int nt = 0; nt < 4; nt++)
                ldsm_x2(b[nt], bB + (uint32_t)(nt * 8 * 80 + ks * 32));
#pragma unroll
            for (int mt = 0; mt < 2; mt++)
#pragma unroll
                for (int nt = 0; nt < 4; nt++)
                    mma16816(acc[mt][nt], a[mt], b[nt]);
        }

        if (kb8 < 7) {
            const int q = p ^ 1;
            *(uint4*)(As + q * 10240 + arow * 80 + apart * 32)      = av0;
            *(uint4*)(As + q * 10240 + arow * 80 + apart * 32 + 16) = av1;
            *(uint4*)(Bs + q * 5120 + brow * 80 + bchunk * 16)      = bv;
        }
        __syncthreads();
        p ^= 1;
    }

    __nv_bfloat16* out = g_gi + (size_t)dir * T_LEN * BATCH * GDIM;
#pragma unroll
    for (int nt = 0; nt < 4; nt++) {
        const int n = n0 + nw + nt * 8 + 2 * tig;
        const float2 bias = *(const float2*)(BV + n);
#pragma unroll
        for (int mt = 0; mt < 2; mt++) {
            const int m = m0 + mw + mt * 16 + gid;
            *(uint32_t*)(out + (size_t)m * GDIM + n) =
                pack_bf16x2(acc[mt][nt][0] + bias.x, acc[mt][nt][1] + bias.y);
            *(uint32_t*)(out + (size_t)(m + 8) * GDIM + n) =
                pack_bf16x2(acc[mt][nt][2] + bias.x, acc[mt][nt][3] + bias.y);
        }
    }
}

// ============================================================================
// K2: persistent bidirectional LSTM (exact R6-proven 1692us version).
//     grid(8,16), cluster(8,1,1), 256 thr.  DO NOT TOUCH.
// ============================================================================
#define K2_WS_BYTES  (128u * 528u)
#define K2_HS_BYTES  (16u * 528u)
#define K2_GX_BYTES  (16u * 132u * 4u)
#define K2_SMEM      (K2_WS_BYTES + K2_HS_BYTES + K2_GX_BYTES)

__global__ void __launch_bounds__(256, 1) __cluster_dims__(8, 1, 1)
k2_lstm()
{
    extern __shared__ __align__(16) unsigned char sm_raw[];
    unsigned char* Wsm  = sm_raw;
    unsigned char* hs16 = sm_raw + K2_WS_BYTES;
    float*         gx   = (float*)(sm_raw + K2_WS_BYTES + K2_HS_BYTES);

    const int tid  = threadIdx.x;
    const int rank = blockIdx.x;
    const int grp  = blockIdx.y & 7;
    const int dir  = blockIdx.y >> 3;
    const int b0   = grp * 16;
    const __nv_bfloat16* Whh16 = g_whh16 + (size_t)dir * GDIM * HDIM;
    const size_t dirH = (size_t)dir * T_LEN * BATCH;

    for (int it = 0; it < 16; it++) {
        const int idx  = tid + it * 256;
        const int row  = idx >> 5;
        const int chnk = idx & 31;
        const int grow = (row >> 5) * 256 + rank * 32 + (row & 31);
        *(uint4*)(Wsm + row * 528 + chnk * 16) =
            *(const uint4*)(Whh16 + (size_t)grow * HDIM + chnk * 8);
    }
    for (int i = tid; i < 528; i += 256) *(uint4*)(hs16 + i * 16) = make_uint4(0,0,0,0);
    __syncthreads();

    const int w = tid >> 5, lane = tid & 31;
    const int gid = lane >> 2, tig = lane & 3;
    const uint32_t hs_b = smem_u32(hs16);
    const uint32_t Ws_b = smem_u32(Wsm);
    const uint32_t aAddrBase = hs_b + (uint32_t)((lane & 15) * 528 + (lane >> 4) * 16);
    const uint32_t bAddr4 = Ws_b + (uint32_t)((w * 16 + ((lane >> 4) & 1) * 8 + (lane & 7)) * 528
                                              + ((lane >> 3) & 1) * 16);

    const int ubb = tid >> 5;
    const int ujj = tid & 31;
    const int goff = rank * 32 + ujj;
    float c0 = 0.f, c1 = 0.f;

    float gir[2][4];
    {
        const int t0 = dir ? (T_LEN - 1) : 0;
        const __nv_bfloat16* gp = g_gi + (dirH + (size_t)t0 * BATCH + b0) * GDIM;
#pragma unroll
        for (int b2 = 0; b2 < 2; b2++)
#pragma unroll
            for (int q = 0; q < 4; q++)
                gir[b2][q] = __bfloat162float(gp[(size_t)(ubb + 8 * b2) * GDIM + q * 256 + goff]);
    }

    for (int s = 0; s < T_LEN; s++) {
        const int t = dir ? (T_LEN - 1 - s) : s;

        float accE[2][4], accO[2][4];
#pragma unroll
        for (int nt = 0; nt < 2; nt++)
#pragma unroll
            for (int r = 0; r < 4; r++) { accE[nt][r] = 0.f; accO[nt][r] = 0.f; }

#pragma unroll
        for (int ks = 0; ks < 16; ks += 2) {
            uint32_t a0[4], a1[4], b0v[4], b1v[4];
            ldsm_x4(a0,  aAddrBase + (uint32_t)(ks * 32));
            ldsm_x4(b0v, bAddr4    + (uint32_t)(ks * 32));
            ldsm_x4(a1,  aAddrBase + (uint32_t)((ks + 1) * 32));
            ldsm_x4(b1v, bAddr4    + (uint32_t)((ks + 1) * 32));
            mma16816(accE[0], a0, b0v);
            mma16816(accE[1], a0, b0v + 2);
            mma16816(accO[0], a1, b1v);
            mma16816(accO[1], a1, b1v + 2);
        }
#pragma unroll
        for (int nt = 0; nt < 2; nt++) {
            const int n = w * 16 + nt * 8 + 2 * tig;
            *(float2*)(gx + gid * 132 + n) =
                make_float2(accE[nt][0] + accO[nt][0], accE[nt][1] + accO[nt][1]);
            *(float2*)(gx + (gid + 8) * 132 + n) =
                make_float2(accE[nt][2] + accO[nt][2], accE[nt][3] + accO[nt][3]);
        }
        __syncthreads();

        float girN[2][4];
        {
            const int sn = (s + 1 < T_LEN) ? (s + 1) : s;
            const int tn = dir ? (T_LEN - 1 - sn) : sn;
            const __nv_bfloat16* gpn = g_gi + (dirH + (size_t)tn * BATCH + b0) * GDIM;
#pragma unroll
            for (int b2 = 0; b2 < 2; b2++)
#pragma unroll
                for (int q = 0; q < 4; q++)
                    girN[b2][q] = __bfloat162float(gpn[(size_t)(ubb + 8 * b2) * GDIM + q * 256 + goff]);
        }

        float xg0[4], xg1[4];
#pragma unroll
        for (int q = 0; q < 4; q++) {
            xg0[q] = gx[(size_t)ubb * 132 + q * 32 + ujj]       + gir[0][q];
            xg1[q] = gx[(size_t)(ubb + 8) * 132 + q * 32 + ujj] + gir[1][q];
        }
        c0 = sig_mufu(xg0[1]) * c0 + sig_mufu(xg0[0]) * tanh_mufu(xg0[2]);
        const float h0 = sig_mufu(xg0[3]) * tanh_mufu(c0);
        c1 = sig_mufu(xg1[1]) * c1 + sig_mufu(xg1[0]) * tanh_mufu(xg1[2]);
        const float h1 = sig_mufu(xg1[3]) * tanh_mufu(c1);

        __nv_bfloat16* hb = g_h16 + (dirH + (size_t)t * BATCH + b0) * HDIM + goff;
        hb[(size_t)ubb * HDIM]       = __float2bfloat16_rn(h0);
        hb[(size_t)(ubb + 8) * HDIM] = __float2bfloat16_rn(h1);

#pragma unroll
        for (int b2 = 0; b2 < 2; b2++)
#pragma unroll
            for (int q = 0; q < 4; q++)
                gir[b2][q] = girN[b2][q];

        CLUSTER_ARRIVE();
        CLUSTER_WAIT();

        {
            const int row = tid >> 4, chnk = tid & 15;
            const uint4* src = (const uint4*)(g_h16 + (dirH + (size_t)t * BATCH + b0 + row) * HDIM
                                              + chnk * 16);
            uint4 v0 = src[0], v1 = src[1];
            *(uint4*)(hs16 + row * 528 + chnk * 32)      = v0;
            *(uint4*)(hs16 + row * 528 + chnk * 32 + 16) = v1;
        }
        __syncthreads();
    }
}

// ============================================================================
// K3: HMMA emissions GEMM (proven). M=65536, N=32, K=512.
// ============================================================================
#define K3_PW_STRIDE 1040u
#define K3_AS_STRIDE 144u
#define K3_PW_BYTES (32u * K3_PW_STRIDE)
#define K3_AS_BYTES (128u * K3_AS_STRIDE)
#define K3_SMEM     (K3_PW_BYTES + K3_AS_BYTES + 128u)

__global__ __launch_bounds__(256) void k3h(const float* __restrict__ pb)
{
    extern __shared__ __align__(16) unsigned char sm[];
    unsigned char* pwS = sm;
    unsigned char* As  = sm + K3_PW_BYTES;
    float*         pbs = (float*)(sm + K3_PW_BYTES + K3_AS_BYTES);

    const int tid = threadIdx.x;
#pragma unroll
    for (int it = 0; it < 8; it++) {
        const int idx = tid + it * 256;
        const int row = idx >> 6, ch = idx & 63;
        *(uint4*)(pwS + row * K3_PW_STRIDE + ch * 16) =
            *(const uint4*)(g_pw16 + (size_t)row * 512 + ch * 8);
    }
    if (tid < 32) pbs[tid] = pb[tid];

    const int w = tid >> 5, lane = tid & 31;
    const int gid = lane >> 2, tig = lane & 3;
    const size_t m0 = (size_t)blockIdx.x * 128;

    float acc[4][4];
#pragma unroll
    for (int nt = 0; nt < 4; nt++)
#pragma unroll
        for (int r = 0; r < 4; r++) acc[nt][r] = 0.f;

    const uint32_t As_b = smem_u32(As), pw_b = smem_u32(pwS);
    const uint32_t aAddr = As_b + (uint32_t)((w * 16 + (lane & 15)) * K3_AS_STRIDE + (lane >> 4) * 16);
    const uint32_t bAddr = pw_b + (uint32_t)((lane & 7) * K3_PW_STRIDE + ((lane >> 3) & 1) * 16);

    __syncthreads();

    for (int kc = 0; kc < 8; kc++) {
        uint4 v[4];
#pragma unroll
        for (int it = 0; it < 4; it++) {
            const int idx = tid + it * 256;
            const int row = idx >> 3, ch = idx & 7;
            const __nv_bfloat16* src = (kc < 4)
                ? g_h16 + (m0 + row) * HDIM + kc * 64
                : g_h16 + ((size_t)T_LEN * BATCH + m0 + row) * HDIM + (kc - 4) * 64;
            v[it] = *(const uint4*)(src + ch * 8);
        }
        __syncthreads();
#pragma unroll
        for (int it = 0; it < 4; it++) {
            const int idx = tid + it * 256;
            const int row = idx >> 3, ch = idx & 7;
            *(uint4*)(As + row * K3_AS_STRIDE + ch * 16) = v[it];
        }
        __syncthreads();

#pragma unroll
        for (int ks = 0; ks < 4; ks++) {
            uint32_t a[4];
            ldsm_x4(a, aAddr + (uint32_t)(ks * 32));
#pragma unroll
            for (int nt = 0; nt < 4; nt++) {
                uint32_t b[2];
                ldsm_x2(b, bAddr + (uint32_t)(nt * 8 * K3_PW_STRIDE + (kc * 4 + ks) * 32));
                mma16816(acc[nt], a, b);
            }
        }
    }

#pragma unroll
    for (int nt = 0; nt < 4; nt++) {
        const int n = nt * 8 + 2 * tig;
        const float2 bias = *(const float2*)(pbs + n);
        const size_t m = m0 + w * 16 + gid;
        *(float2*)(g_em + m * NTAG + n) =
            make_float2(acc[nt][0] + bias.x, acc[nt][1] + bias.y);
        *(float2*)(g_em + (m + 8) * NTAG + n) =
            make_float2(acc[nt][2] + bias.x, acc[nt][3] + bias.y);
    }
}

// ============================================================================
// K4a: CRF forward/backward halves (meet-in-the-middle; halves the serial
//      chain). grid 256 x 32: blocks 0-127 fwd alpha(t=0..255), blocks
//      128-255 bwd beta(t=511..255). Emissions prefetched one step ahead.
// ============================================================================
__global__ __launch_bounds__(32) void k4a(
    const float* __restrict__ st, const float* __restrict__ et,
    const float* __restrict__ tr)
{
    __shared__ float psh[32];
    const int lane = threadIdx.x;
    const int b = blockIdx.x & 127;
    const bool bwd = (blockIdx.x >> 7) != 0;

    if (!bwd) {
        float E[32];
#pragma unroll
        for (int i = 0; i < 32; i++) E[i] = __expf(tr[i * 32 + lane]);

        float al = st[lane] + g_em[(size_t)b * NTAG + lane];
        float em = g_em[((size_t)1 * BATCH + b) * NTAG + lane];
        for (int t = 1; t <= TMID; t++) {
            float emn = 0.f;
            if (t + 1 <= TMID)
                emn = g_em[((size_t)(t + 1) * BATCH + b) * NTAG + lane];
            const float m = __shfl_sync(0xffffffffu, al, 0);
            psh[lane] = __expf(al - m);
            __syncwarp();
            float s0 = 0.f, s1 = 0.f, s2 = 0.f, s3 = 0.f;
#pragma unroll
            for (int i = 0; i < 32; i += 4) {
                s0 += psh[i]     * E[i];
                s1 += psh[i + 1] * E[i + 1];
                s2 += psh[i + 2] * E[i + 2];
                s3 += psh[i + 3] * E[i + 3];
            }
            __syncwarp();
            al = m + __logf((s0 + s1) + (s2 + s3)) + em;
            em = emn;
        }
        g_amid[b * NTAG + lane] = al;
    } else {
        float E[32];   // row of trans: from state `lane` to state i
#pragma unroll
        for (int i = 0; i < 32; i++) E[i] = __expf(tr[lane * 32 + i]);

        float be = et[lane];                                        // beta_{511}
        float em = g_em[((size_t)(T_LEN - 1) * BATCH + b) * NTAG + lane];  // em[511]
        for (int t = T_LEN - 2; t >= TMID; t--) {
            // this iteration computes beta_t from beta_{t+1} using em[t+1]
            float emn = 0.f;
            if (t > TMID)
                emn = g_em[((size_t)t * BATCH + b) * NTAG + lane];  // em[t] for next iter
            const float v = be + em;
            const float m = __shfl_sync(0xffffffffu, v, 0);
            psh[lane] = __expf(v - m);
            __syncwarp();
            float s0 = 0.f, s1 = 0.f, s2 = 0.f, s3 = 0.f;
#pragma unroll
            for (int i = 0; i < 32; i += 4) {
                s0 += psh[i]     * E[i];
                s1 += psh[i + 1] * E[i + 1];
                s2 += psh[i + 2] * E[i + 2];
                s3 += psh[i + 3] * E[i + 3];
            }
            __syncwarp();
            be = m + __logf((s0 + s1) + (s2 + s3));
            em = emn;
        }
        g_bmid[b * NTAG + lane] = be;   // beta_{255}
    }
}

// ============================================================================
// K4b: combine norm = logsumexp(alpha_mid + beta_mid) + numerator score.
//      grid 128 x 32, warp per batch.
// ============================================================================
__global__ __launch_bounds__(32) void k4b(
    const int*   __restrict__ tags,
    const float* __restrict__ st, const float* __restrict__ et,
    const float* __restrict__ tr)
{
    const int lane = threadIdx.x;
    const int b = blockIdx.x;

    float v = g_amid[b * NTAG + lane] + g_bmid[b * NTAG + lane];
    float m = v;
#pragma unroll
    for (int o = 16; o; o >>= 1) m = fmaxf(m, __shfl_xor_sync(0xffffffffu, m, o));
    float s = __expf(v - m);
#pragma unroll
    for (int o = 16; o; o >>= 1) s += __shfl_xor_sync(0xffffffffu, s, o);
    const float norm = m + __logf(s);

    // numerator: prefetch all 16 tags (and prev-tags) first, then gather ems
    int tg[16], tp[16];
#pragma unroll
    for (int k = 0; k < 16; k++) {
        const int t = lane + 32 * k;
        tg[k] = tags[(size_t)t * BATCH + b];
        tp[k] = (t > 0) ? tags[(size_t)(t - 1) * BATCH + b] : 0;
    }
    float sc = 0.f;
#pragma unroll
    for (int k = 0; k < 16; k++) {
        const int t = lane + 32 * k;
        const float e = g_em[((size_t)t * BATCH + b) * NTAG + tg[k]];
        if (t == 0) sc += st[tg[k]] + e;
        else        sc += tr[tp[k] * NTAG + tg[k]] + e;
    }
#pragma unroll
    for (int o = 16; o; o >>= 1) sc += __shfl_xor_sync(0xffffffffu, sc, o);
    if (lane == 0) {
        sc += et[tags[(size_t)(T_LEN - 1) * BATCH + b]];
        g_llh[b] = sc - norm;
    }
}

// K5: deterministic scalar reduce
__global__ void k5_reduce(float* __restrict__ out)
{
    if (threadIdx.x == 0 && blockIdx.x == 0) {
        float s = 0.f;
        for (int b = 0; b < BATCH; b++) s += g_llh[b];
        out[0] = -s;
    }
}

// ============================================================================
extern "C" void kernel_launch(void* const* d_in, const int* in_sizes, int n_in,
                              void* d_out, int out_size)
{
    (void)in_sizes; (void)n_in; (void)out_size;
    const int*   tokens = (const int*)  d_in[0];
    const int*   tags   = (const int*)  d_in[1];
    // d_in[2] = mask (all true; unused)
    const float* embed  = (const float*)d_in[3];
    const float* w_ih_f = (const float*)d_in[4];
    const float* w_hh_f = (const float*)d_in[5];
    const float* b_f    = (const float*)d_in[6];
    const float* w_ih_b = (const float*)d_in[7];
    const float* w_hh_b = (const float*)d_in[8];
    const float* b_b    = (const float*)d_in[9];
    const float* proj_w = (const float*)d_in[10];
    const float* proj_b = (const float*)d_in[11];
    const float* start_trans = (const float*)d_in[12];
    const float* end_trans   = (const float*)d_in[13];
    const float* trans       = (const float*)d_in[14];
    float* out = (float*)d_out;

    cudaFuncSetAttribute(k2_lstm, cudaFuncAttributeMaxDynamicSharedMemorySize, K2_SMEM);
    cudaFuncSetAttribute(k3h,     cudaFuncAttributeMaxDynamicSharedMemorySize, K3_SMEM);

    k0_convert<<<4096, 256>>>(embed, w_ih_f, w_ih_b, w_hh_f, w_hh_b, proj_w);
    k1h<<<dim3(32, 512), 256>>>(tokens, b_f, b_b);
    k2_lstm<<<dim3(8, 16), 256, K2_SMEM>>>();
    k3h<<<512, 256, K3_SMEM>>>(proj_b);
    k4a<<<256, 32>>>(start_trans, end_trans, trans);
    k4b<<<128, 32>>>(tags, start_trans, end_trans, trans);
    k5_reduce<<<1, 32>>>(out);
}